// round 1
// baseline (speedup 1.0000x reference)
#include <cuda_runtime.h>
#include <cstdint>

#define KDIM  8192
#define N4    6144
#define N8    2048
#define NTOT  8192
#define MROWS 16
#define KSEGS 16
#define KSEG  512          // KDIM / KSEGS
#define NBLK  16           // n-blocks (12 int4 + 4 int8)
#define CPB   512          // columns per block
#define TPB   256          // threads per block -> 2 cols/thread

typedef unsigned long long ull;

// Scratch (device globals; no runtime allocation)
__device__ __align__(16) float g_x2[MROWS * KDIM];            // 512 KB
__device__ __align__(16) float g_part[KSEGS][MROWS * NTOT];   // 8 MB partial slabs

// ---- Blackwell packed fp32 FMA (sm_100+: fma.rn.f32x2, not emitted by ptxas from C++) ----
__device__ __forceinline__ ull ffma2(ull a, ull b, ull c) {
    ull d;
    asm("fma.rn.f32x2 %0, %1, %2, %3;" : "=l"(d) : "l"(a), "l"(b), "l"(c));
    return d;
}
__device__ __forceinline__ ull pack2(float lo, float hi) {
    ull r;
    asm("mov.b64 %0, {%1, %2};" : "=l"(r) : "f"(lo), "f"(hi));
    return r;
}
__device__ __forceinline__ float2 unpack2(ull v) {
    float2 f;
    asm("mov.b64 {%0, %1}, %2;" : "=f"(f.x), "=f"(f.y) : "l"(v));
    return f;
}

// ---------------- Kernel 1: x2 = x / awq_scales ----------------
__global__ void prep_kernel(const float* __restrict__ x, const float* __restrict__ awq) {
    int i = blockIdx.x * blockDim.x + threadIdx.x;   // 131072 threads
    g_x2[i] = x[i] / awq[i & (KDIM - 1)];
}

// ---------------- Kernel 2: mixed int4/int8 GEMV ----------------
// grid = (NBLK, KSEGS). Blocks 0..11: int4 columns. Blocks 12..15: uint8 columns.
// Each thread: 2 columns, 16 m accumulators per column as f32x2 (k-pair packed).
__global__ void __launch_bounds__(TPB, 2) gemv_kernel(
    const int4* __restrict__ w4,   // w_int4 viewed as int4 vectors
    const float* __restrict__ s4,  // s_int4 [N4][64]
    const int4* __restrict__ w8)   // w_uint8 viewed as int4 vectors
{
    __shared__ ull xs[MROWS][KSEG / 2];   // 16 x 256 x 8B = 32 KB, pre-paired x2

    const int nb  = blockIdx.x;
    const int ks  = blockIdx.y;
    const int k0  = ks * KSEG;
    const int tid = threadIdx.x;

    // Stage x2 tile into smem as (x[2kp], x[2kp+1]) pairs
    {
        const float2* src = reinterpret_cast<const float2*>(g_x2);
        #pragma unroll
        for (int i = tid; i < MROWS * (KSEG / 2); i += TPB) {
            int m = i >> 8;            // /256
            int j = i & 255;
            float2 v = src[m * (KDIM / 2) + (k0 >> 1) + j];
            xs[m][j] = pack2(v.x, v.y);
        }
    }
    __syncthreads();

    ull acc0[MROWS], acc1[MROWS];
    #pragma unroll
    for (int m = 0; m < MROWS; m++) { acc0[m] = 0ull; acc1[m] = 0ull; }

    if (nb < 12) {
        // ---------------- int4 path ----------------
        const int n0 = nb * CPB + tid;
        const int n1 = n0 + TPB;
        const int4* r0 = w4 + ((size_t)n0 * KDIM + k0) / 4;
        const int4* r1 = w4 + ((size_t)n1 * KDIM + k0) / 4;

        #pragma unroll
        for (int g = 0; g < KSEG / 128; g++) {
            const int gidx = (k0 >> 7) + g;
            const float sa = s4[n0 * (KDIM / 128) + gidx];
            const float sb = s4[n1 * (KDIM / 128) + gidx];
            const ull sad = pack2(sa, sa);
            const ull msa = pack2(-8.0f * sa, -8.0f * sa);
            const ull sbd = pack2(sb, sb);
            const ull msb = pack2(-8.0f * sb, -8.0f * sb);

            #pragma unroll 4
            for (int it = 0; it < 32; it++) {        // 4 k per iteration
                const int idx = g * 32 + it;
                const int4 wa = r0[idx];
                const int4 wb = r1[idx];
                // dequant: (w-8)*s folded into one packed FMA: w*s + (-8s)
                ull wa01 = pack2(__int2float_rn(wa.x), __int2float_rn(wa.y));
                ull wa23 = pack2(__int2float_rn(wa.z), __int2float_rn(wa.w));
                ull wb01 = pack2(__int2float_rn(wb.x), __int2float_rn(wb.y));
                ull wb23 = pack2(__int2float_rn(wb.z), __int2float_rn(wb.w));
                wa01 = ffma2(wa01, sad, msa);
                wa23 = ffma2(wa23, sad, msa);
                wb01 = ffma2(wb01, sbd, msb);
                wb23 = ffma2(wb23, sbd, msb);

                const int kp = idx * 2;
                #pragma unroll
                for (int m = 0; m < MROWS; m++) {
                    const ull xp0 = xs[m][kp];        // warp-uniform broadcast LDS
                    const ull xp1 = xs[m][kp + 1];
                    acc0[m] = ffma2(xp0, wa01, acc0[m]);
                    acc0[m] = ffma2(xp1, wa23, acc0[m]);
                    acc1[m] = ffma2(xp0, wb01, acc1[m]);
                    acc1[m] = ffma2(xp1, wb23, acc1[m]);
                }
            }
        }

        float* dst = &g_part[ks][0];
        #pragma unroll
        for (int m = 0; m < MROWS; m++) {
            float2 a = unpack2(acc0[m]);
            float2 b = unpack2(acc1[m]);
            dst[m * NTOT + n0] = a.x + a.y;
            dst[m * NTOT + n1] = b.x + b.y;
        }
    } else {
        // ---------------- uint8 path: sum x2*(w-128); s8 scale deferred ----------------
        const int nl0 = (nb - 12) * CPB + tid;
        const int nl1 = nl0 + TPB;
        const int4* r0 = w8 + ((size_t)nl0 * KDIM + k0) / 4;
        const int4* r1 = w8 + ((size_t)nl1 * KDIM + k0) / 4;

        #pragma unroll 4
        for (int idx = 0; idx < KSEG / 4; idx++) {
            const int4 wa = r0[idx];
            const int4 wb = r1[idx];
            const ull wa01 = pack2(__int2float_rn(wa.x - 128), __int2float_rn(wa.y - 128));
            const ull wa23 = pack2(__int2float_rn(wa.z - 128), __int2float_rn(wa.w - 128));
            const ull wb01 = pack2(__int2float_rn(wb.x - 128), __int2float_rn(wb.y - 128));
            const ull wb23 = pack2(__int2float_rn(wb.z - 128), __int2float_rn(wb.w - 128));

            const int kp = idx * 2;
            #pragma unroll
            for (int m = 0; m < MROWS; m++) {
                const ull xp0 = xs[m][kp];
                const ull xp1 = xs[m][kp + 1];
                acc0[m] = ffma2(xp0, wa01, acc0[m]);
                acc0[m] = ffma2(xp1, wa23, acc0[m]);
                acc1[m] = ffma2(xp0, wb01, acc1[m]);
                acc1[m] = ffma2(xp1, wb23, acc1[m]);
            }
        }

        float* dst = &g_part[ks][0];
        #pragma unroll
        for (int m = 0; m < MROWS; m++) {
            float2 a = unpack2(acc0[m]);
            float2 b = unpack2(acc1[m]);
            dst[m * NTOT + N4 + nl0] = a.x + a.y;
            dst[m * NTOT + N4 + nl1] = b.x + b.y;
        }
    }
}

// ---------------- Kernel 3: slab reduce + s8 scale + inverse perm + bias ----------------
__global__ void epilogue_kernel(const float* __restrict__ s8,
                                const float* __restrict__ bias,
                                const int* __restrict__ inv_perm,
                                float* __restrict__ out)
{
    const int j = blockIdx.x * blockDim.x + threadIdx.x;   // 8192
    const int p = inv_perm[j];
    const float s = (p >= N4) ? s8[p - N4] : 1.0f;
    const float b = bias[j];
    #pragma unroll
    for (int m = 0; m < MROWS; m++) {
        float v = 0.0f;
        #pragma unroll
        for (int ksg = 0; ksg < KSEGS; ksg++)
            v += g_part[ksg][m * NTOT + p];
        out[m * NTOT + j] = v * s + b;
    }
}

extern "C" void kernel_launch(void* const* d_in, const int* in_sizes, int n_in,
                              void* d_out, int out_size)
{
    const float* x    = (const float*)d_in[0];
    const int*   w4   = (const int*)  d_in[1];
    const float* s4   = (const float*)d_in[2];
    const int*   w8   = (const int*)  d_in[3];
    const float* s8   = (const float*)d_in[4];
    const float* awq  = (const float*)d_in[5];
    const float* bias = (const float*)d_in[6];
    const int*   ip   = (const int*)  d_in[7];
    float* out = (float*)d_out;

    prep_kernel<<<(MROWS * KDIM) / 256, 256>>>(x, awq);

    dim3 grid(NBLK, KSEGS);
    gemv_kernel<<<grid, TPB>>>((const int4*)w4, s4, (const int4*)w8);

    epilogue_kernel<<<NTOT / 256, 256>>>(s8, bias, ip, out);
}

// round 2
// speedup vs baseline: 1.0950x; 1.0950x over previous
#include <cuda_runtime.h>
#include <cstdint>

#define KDIM  8192
#define N4    6144
#define N8    2048
#define NTOT  8192
#define MROWS 16
#define KSEGS 8
#define KSEG  1024         // KDIM / KSEGS
#define NBLK  32           // 24 int4 blocks + 8 int8 blocks
#define CPB   256          // columns per block (1 per thread)
#define TPB   256
#define NGROUPS_SEG 8      // KSEG / 128

typedef unsigned long long ull;

// Scratch (device globals; no runtime allocation)
__device__ __align__(16) float g_x2[MROWS * KDIM];            // 512 KB
__device__ __align__(16) float g_part[KSEGS][MROWS * NTOT];   // 4 MB partial slabs

// ---- Blackwell packed fp32 ops (sm_100+; ptxas never auto-emits these) ----
__device__ __forceinline__ ull ffma2(ull a, ull b, ull c) {
    ull d;
    asm("fma.rn.f32x2 %0, %1, %2, %3;" : "=l"(d) : "l"(a), "l"(b), "l"(c));
    return d;
}
__device__ __forceinline__ ull fadd2(ull a, ull b) {
    ull d;
    asm("add.rn.f32x2 %0, %1, %2;" : "=l"(d) : "l"(a), "l"(b));
    return d;
}
__device__ __forceinline__ ull pack2(float lo, float hi) {
    ull r;
    asm("mov.b64 %0, {%1, %2};" : "=l"(r) : "f"(lo), "f"(hi));
    return r;
}
__device__ __forceinline__ float2 unpack2(ull v) {
    float2 f;
    asm("mov.b64 {%0, %1}, %2;" : "=f"(f.x), "=f"(f.y) : "l"(v));
    return f;
}
// int (0 <= w < 2^22) -> float(2^23 + w), exact, one LOP3 on the alu pipe
__device__ __forceinline__ float biasf(int w) {
    return __uint_as_float(0x4B000000u | (unsigned)w);
}

// ---------------- Kernel 1: x2 = x / awq_scales ----------------
__global__ void prep_kernel(const float* __restrict__ x, const float* __restrict__ awq) {
    int i = blockIdx.x * blockDim.x + threadIdx.x;   // 131072 threads
    g_x2[i] = x[i] / awq[i & (KDIM - 1)];
}

// ---------------- Kernel 2: mixed int4/int8 GEMV ----------------
// grid = (NBLK, KSEGS). Blocks 0..23: int4 columns. Blocks 24..31: uint8 cols.
// 1 column/thread; all 16 m rows as k-pair-packed f32x2 group accumulators.
__global__ void __launch_bounds__(TPB, 2) gemv_kernel(
    const int4* __restrict__ w4,   // w_int4 as int4 vectors
    const float* __restrict__ s4,  // s_int4 [N4][64]
    const int4* __restrict__ w8)   // w_uint8 as int4 vectors
{
    __shared__ ull xs[MROWS][KSEG / 2];   // 16 x 512 x 8B = 64 KB, pre-paired x2

    const int nb  = blockIdx.x;
    const int ks  = blockIdx.y;
    const int k0  = ks * KSEG;
    const int tid = threadIdx.x;

    // Stage x2 tile into smem as (x[2kp], x[2kp+1]) pairs, 16B stores
    {
        const float4* src = reinterpret_cast<const float4*>(g_x2);
        #pragma unroll
        for (int i = tid; i < MROWS * (KSEG / 4); i += TPB) {
            int m = i >> 8;            // / 256
            int j = i & 255;
            float4 v = src[m * (KDIM / 4) + (k0 >> 2) + j];
            ulonglong2 p;
            p.x = pack2(v.x, v.y);
            p.y = pack2(v.z, v.w);
            reinterpret_cast<ulonglong2*>(&xs[m][0])[j] = p;
        }
    }
    __syncthreads();

    if (nb < 24) {
        // ---------------- int4 path ----------------
        const int n = nb * CPB + tid;
        const int4* row = w4 + ((size_t)n * KDIM + k0) / 4;
        const ull C4 = pack2(-8388616.0f, -8388616.0f);   // -(2^23 + 8)

        float acc[MROWS];
        #pragma unroll
        for (int m = 0; m < MROWS; m++) acc[m] = 0.0f;

        #pragma unroll
        for (int g = 0; g < NGROUPS_SEG; g++) {
            const float s = s4[n * (KDIM / 128) + (k0 >> 7) + g];

            ull accg[MROWS];
            #pragma unroll
            for (int m = 0; m < MROWS; m++) accg[m] = 0ull;

            #pragma unroll 8
            for (int it = 0; it < 32; it++) {            // 4 k per iter
                const int idx = g * 32 + it;
                const int4 w = __ldcs(row + idx);
                // exact (w - 8) as packed f32x2: LOP3 + packed add (no I2F)
                const ull w01 = fadd2(pack2(biasf(w.x), biasf(w.y)), C4);
                const ull w23 = fadd2(pack2(biasf(w.z), biasf(w.w)), C4);

                const int kp = idx * 2;
                #pragma unroll
                for (int m = 0; m < MROWS; m++) {
                    const ulonglong2 xp =
                        *reinterpret_cast<const ulonglong2*>(&xs[m][kp]);
                    accg[m] = ffma2(xp.x, w01, accg[m]);
                    accg[m] = ffma2(xp.y, w23, accg[m]);
                }
            }
            // fold group scale once per 128 k
            #pragma unroll
            for (int m = 0; m < MROWS; m++) {
                float2 t = unpack2(accg[m]);
                acc[m] = fmaf(t.x + t.y, s, acc[m]);
            }
        }

        float* dst = &g_part[ks][0];
        #pragma unroll
        for (int m = 0; m < MROWS; m++)
            dst[m * NTOT + n] = acc[m];
    } else {
        // ---------------- uint8 path: sum x2*(w-128); s8 deferred ----------------
        const int nl = (nb - 24) * CPB + tid;
        const int4* row = w8 + ((size_t)nl * KDIM + k0) / 4;
        const ull C8 = pack2(-8388736.0f, -8388736.0f);   // -(2^23 + 128)

        ull accp[MROWS];
        #pragma unroll
        for (int m = 0; m < MROWS; m++) accp[m] = 0ull;

        #pragma unroll 8
        for (int idx = 0; idx < KSEG / 4; idx++) {
            const int4 w = __ldcs(row + idx);
            const ull w01 = fadd2(pack2(biasf(w.x), biasf(w.y)), C8);
            const ull w23 = fadd2(pack2(biasf(w.z), biasf(w.w)), C8);

            const int kp = idx * 2;
            #pragma unroll
            for (int m = 0; m < MROWS; m++) {
                const ulonglong2 xp =
                    *reinterpret_cast<const ulonglong2*>(&xs[m][kp]);
                accp[m] = ffma2(xp.x, w01, accp[m]);
                accp[m] = ffma2(xp.y, w23, accp[m]);
            }
        }

        float* dst = &g_part[ks][0];
        #pragma unroll
        for (int m = 0; m < MROWS; m++) {
            float2 t = unpack2(accp[m]);
            dst[m * NTOT + N4 + nl] = t.x + t.y;
        }
    }
}

// ---------------- Kernel 3: slab reduce + s8 scale + inverse perm + bias ----------------
__global__ void epilogue_kernel(const float* __restrict__ s8,
                                const float* __restrict__ bias,
                                const int* __restrict__ inv_perm,
                                float* __restrict__ out)
{
    const int j = blockIdx.x * blockDim.x + threadIdx.x;   // 8192
    const int p = inv_perm[j];
    const float s = (p >= N4) ? s8[p - N4] : 1.0f;
    const float b = bias[j];
    #pragma unroll
    for (int m = 0; m < MROWS; m++) {
        float v = 0.0f;
        #pragma unroll
        for (int ksg = 0; ksg < KSEGS; ksg++)
            v += g_part[ksg][m * NTOT + p];
        out[m * NTOT + j] = v * s + b;
    }
}

extern "C" void kernel_launch(void* const* d_in, const int* in_sizes, int n_in,
                              void* d_out, int out_size)
{
    const float* x    = (const float*)d_in[0];
    const int*   w4   = (const int*)  d_in[1];
    const float* s4   = (const float*)d_in[2];
    const int*   w8   = (const int*)  d_in[3];
    const float* s8   = (const float*)d_in[4];
    const float* awq  = (const float*)d_in[5];
    const float* bias = (const float*)d_in[6];
    const int*   ip   = (const int*)  d_in[7];
    float* out = (float*)d_out;

    prep_kernel<<<(MROWS * KDIM) / 256, 256>>>(x, awq);

    dim3 grid(NBLK, KSEGS);
    gemv_kernel<<<grid, TPB>>>((const int4*)w4, s4, (const int4*)w8);

    epilogue_kernel<<<NTOT / 256, 256>>>(s8, bias, ip, out);
}

// round 3
// speedup vs baseline: 1.4772x; 1.3490x over previous
#include <cuda_runtime.h>
#include <cstdint>

#define KDIM  8192
#define N4    6144
#define N8    2048
#define NTOT  8192
#define MROWS 16
#define KSEGS 16
#define KSEG  512          // KDIM / KSEGS
#define NBLK  16           // 12 int4 + 4 int8 column blocks
#define TPB   128
#define CPT   4            // columns per thread
#define CPB   (TPB * CPT)  // 512 columns per block

typedef unsigned long long ull;

// Scratch (device globals; no runtime allocation)
__device__ __align__(16) float  g_x2t[KDIM * MROWS];              // 512 KB, [k][m]
__device__ __align__(16) float2 g_part[KSEGS][MROWS / 2][NTOT];   // 8 MB, [ks][mp][n]

// ---- Blackwell packed fp32 ops (sm_100+; ptxas never auto-emits these) ----
__device__ __forceinline__ ull ffma2(ull a, ull b, ull c) {
    ull d;
    asm("fma.rn.f32x2 %0, %1, %2, %3;" : "=l"(d) : "l"(a), "l"(b), "l"(c));
    return d;
}
__device__ __forceinline__ ull pack2(float lo, float hi) {
    ull r;
    asm("mov.b64 %0, {%1, %2};" : "=l"(r) : "f"(lo), "f"(hi));
    return r;
}
__device__ __forceinline__ float2 unpack2(ull v) {
    float2 f;
    asm("mov.b64 {%0, %1}, %2;" : "=f"(f.x), "=f"(f.y) : "l"(v));
    return f;
}
// int (0 <= w < 2^22) -> float(2^23 + w), exact, one LOP3
__device__ __forceinline__ float biasf(int w) {
    return __uint_as_float(0x4B000000u | (unsigned)w);
}

// ---------------- Kernel 1: x2t[k][m] = x[m][k] / awq[k] (transpose) ----------------
__global__ void prep_kernel(const float* __restrict__ x, const float* __restrict__ awq) {
    const int k = blockIdx.x * blockDim.x + threadIdx.x;   // 8192 threads
    const float inv = 1.0f / awq[k];   // full-precision reciprocal path
    float v[MROWS];
    #pragma unroll
    for (int m = 0; m < MROWS; m++)
        v[m] = x[m * KDIM + k] * 0.0f + x[m * KDIM + k] / awq[k];  // keep exact division
    // NOTE: the line above would double-compute; do it plainly instead:
    #pragma unroll
    for (int m = 0; m < MROWS; m++)
        v[m] = x[m * KDIM + k] / awq[k];
    (void)inv;
    float4* dst = reinterpret_cast<float4*>(g_x2t + (size_t)k * MROWS);
    #pragma unroll
    for (int q = 0; q < 4; q++)
        dst[q] = make_float4(v[4 * q], v[4 * q + 1], v[4 * q + 2], v[4 * q + 3]);
}

// ---------------- Kernel 2: mixed int4/int8 GEMV ----------------
// grid = (NBLK, KSEGS). Blocks 0..11: int4 cols. Blocks 12..15: uint8 cols.
// Each thread: 4 columns, 16 m rows as m-pair-packed f32x2 accumulators.
__global__ void __launch_bounds__(TPB, 2) gemv_kernel(
    const int4* __restrict__ w4,   // w_int4 as int4 vectors
    const float* __restrict__ s4,  // s_int4 [N4][64]
    const int4* __restrict__ w8)   // w_uint8 as int4 vectors
{
    __shared__ ull xs[KSEG][MROWS / 2];   // [k][m-pair], 512*8*8B = 32 KB

    const int nb  = blockIdx.x;
    const int ks  = blockIdx.y;
    const int k0  = ks * KSEG;
    const int tid = threadIdx.x;

    // Stage transposed x tile: 32 KB contiguous copy
    {
        const float4* src = reinterpret_cast<const float4*>(g_x2t + (size_t)k0 * MROWS);
        float4* dst = reinterpret_cast<float4*>(&xs[0][0]);
        #pragma unroll
        for (int i = tid; i < KSEG * MROWS / 4; i += TPB)
            dst[i] = src[i];
    }
    __syncthreads();

    ull acc[CPT][MROWS / 2];
    #pragma unroll
    for (int c = 0; c < CPT; c++)
        #pragma unroll
        for (int mp = 0; mp < MROWS / 2; mp++) acc[c][mp] = 0ull;

    if (nb < 12) {
        // ---------------- int4 path ----------------
        int n[CPT];
        const int4* row[CPT];
        #pragma unroll
        for (int c = 0; c < CPT; c++) {
            n[c] = nb * CPB + c * TPB + tid;          // coalesced across warp
            row[c] = w4 + ((size_t)n[c] * KDIM + k0) / 4;
        }
        const float C4 = -8388616.0f;                 // -(2^23 + 8)

        #pragma unroll
        for (int g = 0; g < KSEG / 128; g++) {        // 4 groups of 128 k
            float s[CPT];
            #pragma unroll
            for (int c = 0; c < CPT; c++)
                s[c] = s4[n[c] * (KDIM / 128) + (k0 >> 7) + g];

            #pragma unroll 2
            for (int it = 0; it < 32; it++) {         // 4 k per iteration
                const int idx = g * 32 + it;
                int4 w[CPT];
                #pragma unroll
                for (int c = 0; c < CPT; c++) w[c] = __ldcs(row[c] + idx);

                #pragma unroll
                for (int j = 0; j < 4; j++) {
                    const int k = idx * 4 + j;
                    ulonglong2 xa = *reinterpret_cast<const ulonglong2*>(&xs[k][0]);
                    ulonglong2 xb = *reinterpret_cast<const ulonglong2*>(&xs[k][2]);
                    ulonglong2 xc = *reinterpret_cast<const ulonglong2*>(&xs[k][4]);
                    ulonglong2 xd = *reinterpret_cast<const ulonglong2*>(&xs[k][6]);
                    #pragma unroll
                    for (int c = 0; c < CPT; c++) {
                        const int wi = (j == 0) ? w[c].x : (j == 1) ? w[c].y
                                     : (j == 2) ? w[c].z : w[c].w;
                        const float wd = (biasf(wi) + C4) * s[c];   // exact (w-8)*s
                        const ull wdd = pack2(wd, wd);
                        acc[c][0] = ffma2(xa.x, wdd, acc[c][0]);
                        acc[c][1] = ffma2(xa.y, wdd, acc[c][1]);
                        acc[c][2] = ffma2(xb.x, wdd, acc[c][2]);
                        acc[c][3] = ffma2(xb.y, wdd, acc[c][3]);
                        acc[c][4] = ffma2(xc.x, wdd, acc[c][4]);
                        acc[c][5] = ffma2(xc.y, wdd, acc[c][5]);
                        acc[c][6] = ffma2(xd.x, wdd, acc[c][6]);
                        acc[c][7] = ffma2(xd.y, wdd, acc[c][7]);
                    }
                }
            }
        }

        #pragma unroll
        for (int c = 0; c < CPT; c++)
            #pragma unroll
            for (int mp = 0; mp < MROWS / 2; mp++) {
                float2 t = unpack2(acc[c][mp]);
                g_part[ks][mp][n[c]] = t;
            }
    } else {
        // ---------------- uint8 path: sum x2*(w-128); s8 deferred ----------------
        int nl[CPT];
        const int4* row[CPT];
        #pragma unroll
        for (int c = 0; c < CPT; c++) {
            nl[c] = (nb - 12) * CPB + c * TPB + tid;
            row[c] = w8 + ((size_t)nl[c] * KDIM + k0) / 4;
        }
        const float C8 = -8388736.0f;                 // -(2^23 + 128)

        #pragma unroll 2
        for (int idx = 0; idx < KSEG / 4; idx++) {
            int4 w[CPT];
            #pragma unroll
            for (int c = 0; c < CPT; c++) w[c] = __ldcs(row[c] + idx);

            #pragma unroll
            for (int j = 0; j < 4; j++) {
                const int k = idx * 4 + j;
                ulonglong2 xa = *reinterpret_cast<const ulonglong2*>(&xs[k][0]);
                ulonglong2 xb = *reinterpret_cast<const ulonglong2*>(&xs[k][2]);
                ulonglong2 xc = *reinterpret_cast<const ulonglong2*>(&xs[k][4]);
                ulonglong2 xd = *reinterpret_cast<const ulonglong2*>(&xs[k][6]);
                #pragma unroll
                for (int c = 0; c < CPT; c++) {
                    const int wi = (j == 0) ? w[c].x : (j == 1) ? w[c].y
                                 : (j == 2) ? w[c].z : w[c].w;
                    const float wd = biasf(wi) + C8;            // exact w-128
                    const ull wdd = pack2(wd, wd);
                    acc[c][0] = ffma2(xa.x, wdd, acc[c][0]);
                    acc[c][1] = ffma2(xa.y, wdd, acc[c][1]);
                    acc[c][2] = ffma2(xb.x, wdd, acc[c][2]);
                    acc[c][3] = ffma2(xb.y, wdd, acc[c][3]);
                    acc[c][4] = ffma2(xc.x, wdd, acc[c][4]);
                    acc[c][5] = ffma2(xc.y, wdd, acc[c][5]);
                    acc[c][6] = ffma2(xd.x, wdd, acc[c][6]);
                    acc[c][7] = ffma2(xd.y, wdd, acc[c][7]);
                }
            }
        }

        #pragma unroll
        for (int c = 0; c < CPT; c++)
            #pragma unroll
            for (int mp = 0; mp < MROWS / 2; mp++) {
                float2 t = unpack2(acc[c][mp]);
                g_part[ks][mp][N4 + nl[c]] = t;
            }
    }
}

// ---------------- Kernel 3: slab reduce + s8 scale + inverse perm + bias ----------------
__global__ void epilogue_kernel(const float* __restrict__ s8,
                                const float* __restrict__ bias,
                                const int* __restrict__ inv_perm,
                                float* __restrict__ out)
{
    const int j = blockIdx.x * blockDim.x + threadIdx.x;   // 8192
    const int p = inv_perm[j];
    const float s = (p >= N4) ? s8[p - N4] : 1.0f;
    const float b = bias[j];

    float2 v[MROWS / 2];
    #pragma unroll
    for (int mp = 0; mp < MROWS / 2; mp++) v[mp] = make_float2(0.0f, 0.0f);

    #pragma unroll
    for (int ksg = 0; ksg < KSEGS; ksg++)
        #pragma unroll
        for (int mp = 0; mp < MROWS / 2; mp++) {
            float2 t = g_part[ksg][mp][p];
            v[mp].x += t.x;
            v[mp].y += t.y;
        }

    #pragma unroll
    for (int mp = 0; mp < MROWS / 2; mp++) {
        out[(2 * mp)     * NTOT + j] = v[mp].x * s + b;
        out[(2 * mp + 1) * NTOT + j] = v[mp].y * s + b;
    }
}

extern "C" void kernel_launch(void* const* d_in, const int* in_sizes, int n_in,
                              void* d_out, int out_size)
{
    const float* x    = (const float*)d_in[0];
    const int*   w4   = (const int*)  d_in[1];
    const float* s4   = (const float*)d_in[2];
    const int*   w8   = (const int*)  d_in[3];
    const float* s8   = (const float*)d_in[4];
    const float* awq  = (const float*)d_in[5];
    const float* bias = (const float*)d_in[6];
    const int*   ip   = (const int*)  d_in[7];
    float* out = (float*)d_out;

    prep_kernel<<<KDIM / 256, 256>>>(x, awq);

    dim3 grid(NBLK, KSEGS);
    gemv_kernel<<<grid, TPB>>>((const int4*)w4, s4, (const int4*)w8);

    epilogue_kernel<<<NTOT / 256, 256>>>(s8, bias, ip, out);
}